// round 2
// baseline (speedup 1.0000x reference)
#include <cuda_runtime.h>
#include <cstdint>

// Bloom filter: NUM_BITS = 2^27, NUM_HASHES = 7, PRIME = 2654435761.
// Positions for value v: (v*PRIME + s) & (2^27-1), s = 0..6 -> 7 CONSECUTIVE
// bits starting at h = (v*PRIME) & MASK (mod 2^27). Low 27 bits of the int64
// product equal the low 27 bits of the 32-bit wrapping product (v < 2^31),
// so a single 32-bit IMAD computes the hash.
//
// Harness dtypes: inputs are the int64 values canonicalized to int32 OR kept
// as int64 — detected at runtime (high words all-zero <=> 8-byte storage).
// Output is float32 (0.0 / 1.0).

#define NUM_BITS   (1u << 27)
#define BIT_MASK   (NUM_BITS - 1u)
#define PRIME      2654435761u
#define NUM_WORDS  (NUM_BITS / 64u)        // 2^21 x 64-bit words = 16 MB
#define WORD_MASK  (NUM_WORDS - 1u)

__device__ unsigned long long g_bits[NUM_WORDS];
__device__ int g_wide;   // 1 -> inputs stored as 8-byte ints, 0 -> 4-byte

// --------------------------------------------------------------- detect ----
// If values are stored as int64 (little-endian, all < 2^31), every odd int32
// word is zero. If stored as int32, odd words are random values: the chance
// that 4096 of them are all zero is ~0. Deterministic for fixed inputs.
__global__ void detect_kernel(const int* __restrict__ a) {
    __shared__ int s_any;
    if (threadIdx.x == 0) s_any = 0;
    __syncthreads();
    int acc = 0;
    for (int i = threadIdx.x; i < 4096; i += blockDim.x)
        acc |= a[2 * i + 1];
    if (acc) atomicOr(&s_any, 1);
    __syncthreads();
    if (threadIdx.x == 0) g_wide = (s_any == 0) ? 1 : 0;
}

// ---------------------------------------------------------------- clear ----
__global__ void clear_kernel() {
    const unsigned int n2 = NUM_WORDS / 2;
    ulonglong2* p = reinterpret_cast<ulonglong2*>(g_bits);
    const ulonglong2 z = make_ulonglong2(0ull, 0ull);
    for (unsigned int i = blockIdx.x * blockDim.x + threadIdx.x; i < n2;
         i += gridDim.x * blockDim.x)
        p[i] = z;
}

// ------------------------------------------------------------------ add ----
__global__ void add_kernel(const int* __restrict__ vals, int n) {
    int i = blockIdx.x * blockDim.x + threadIdx.x;
    if (i >= n) return;
    const int stride = g_wide ? 2 : 1;          // int64 storage: low word at 2*i
    unsigned int v   = (unsigned int)vals[i * stride];
    unsigned int pos = (v * PRIME) & BIT_MASK;
    unsigned int w   = pos >> 6;
    unsigned int b   = pos & 63u;
    atomicOr(&g_bits[w], 0x7Full << b);          // bits >=64 shift out naturally
    if (b > 57u)
        atomicOr(&g_bits[(w + 1u) & WORD_MASK], 0x7Full >> (64u - b));
}

// ---------------------------------------------------------------- query ----
__global__ void query_kernel(const int* __restrict__ q,
                             float* __restrict__ out, int n) {
    int i = blockIdx.x * blockDim.x + threadIdx.x;
    if (i >= n) return;
    const int stride = g_wide ? 2 : 1;
    unsigned int v   = (unsigned int)q[i * stride];
    unsigned int pos = (v * PRIME) & BIT_MASK;
    unsigned int w   = pos >> 6;
    unsigned int b   = pos & 63u;
    unsigned long long field = g_bits[w] >> b;
    if (b > 57u)
        field |= g_bits[(w + 1u) & WORD_MASK] << (64u - b);
    out[i] = ((field & 0x7Full) == 0x7Full) ? 1.0f : 0.0f;
}

// ------------------------------------------------------------- launcher ----
extern "C" void kernel_launch(void* const* d_in, const int* in_sizes, int n_in,
                              void* d_out, int out_size) {
    const int* add_values   = (const int*)d_in[0];
    const int* query_values = (const int*)d_in[1];
    float*     out          = (float*)d_out;
    int n_add = in_sizes[0];
    int n_qry = in_sizes[1];

    detect_kernel<<<1, 256>>>(add_values);
    clear_kernel<<<2048, 256>>>();
    add_kernel<<<(n_add + 255) / 256, 256>>>(add_values, n_add);
    query_kernel<<<(n_qry + 255) / 256, 256>>>(query_values, out, n_qry);
}

// round 3
// speedup vs baseline: 1.0932x; 1.0932x over previous
#include <cuda_runtime.h>
#include <cstdint>

// Bloom filter: NUM_BITS = 2^27, NUM_HASHES = 7, PRIME = 2654435761.
// Positions for value v: (v*PRIME + s) & (2^27-1), s=0..6 -> 7 CONSECUTIVE
// bits starting at h = (v*PRIME) & MASK. Low 27 bits of the int64 product
// equal those of the 32-bit wrapping product (v < 2^31): one IMAD per hash.
//
// Inputs may be stored as int64 or canonicalized int32 — detected on device
// (high words all-zero over 4096 pairs <=> 8-byte storage). Output: float32.

#define NUM_BITS   (1u << 27)
#define BIT_MASK   (NUM_BITS - 1u)
#define PRIME      2654435761u
#define NUM_WORDS  (NUM_BITS / 64u)        // 2^21 x u64 = 16 MB (L2-resident)
#define WORD_MASK  (NUM_WORDS - 1u)
#define CHUNKS     (NUM_WORDS / 2u)        // 128-bit chunks

__device__ unsigned long long g_bits[NUM_WORDS];
__device__ int g_wide;   // 1 -> 8-byte input storage, 0 -> 4-byte

// --------------------------------------------------- clear (+ detect) ----
// Block 0 detects input width; all blocks zero the bitset (64B/thread/iter).
__global__ void clear_kernel(const int* __restrict__ a) {
    if (blockIdx.x == 0) {
        __shared__ int s_any;
        if (threadIdx.x == 0) s_any = 0;
        __syncthreads();
        int acc = 0;
        for (int i = threadIdx.x; i < 4096; i += blockDim.x)
            acc |= a[2 * i + 1];
        if (acc) atomicOr(&s_any, 1);
        __syncthreads();
        if (threadIdx.x == 0) g_wide = (s_any == 0) ? 1 : 0;
    }
    const unsigned int n4 = NUM_WORDS / 2;        // ulonglong2 elements
    ulonglong2* p = reinterpret_cast<ulonglong2*>(g_bits);
    const ulonglong2 z = make_ulonglong2(0ull, 0ull);
    for (unsigned int i = blockIdx.x * blockDim.x + threadIdx.x; i < n4;
         i += gridDim.x * blockDim.x)
        p[i] = z;
}

// ---------------------------------------------------------------- add ----
__device__ __forceinline__ void do_add(unsigned int v) {
    unsigned int pos = (v * PRIME) & BIT_MASK;
    unsigned int w   = pos >> 6;
    unsigned int b   = pos & 63u;
    atomicOr(&g_bits[w], 0x7Full << b);           // bits >=64 shift out
    if (b > 57u)
        atomicOr(&g_bits[(w + 1u) & WORD_MASK], 0x7Full >> (64u - b));
}

__global__ void add_kernel(const int* __restrict__ vals, int n) {
    int base = (blockIdx.x * blockDim.x + threadIdx.x) * 4;
    if (base + 3 < n) {
        unsigned int v0, v1, v2, v3;
        if (g_wide) {
            int4 a = *reinterpret_cast<const int4*>(vals + 2 * base);
            int4 b = *reinterpret_cast<const int4*>(vals + 2 * base + 4);
            v0 = (unsigned)a.x; v1 = (unsigned)a.z;
            v2 = (unsigned)b.x; v3 = (unsigned)b.z;
        } else {
            int4 a = *reinterpret_cast<const int4*>(vals + base);
            v0 = (unsigned)a.x; v1 = (unsigned)a.y;
            v2 = (unsigned)a.z; v3 = (unsigned)a.w;
        }
        do_add(v0); do_add(v1); do_add(v2); do_add(v3);
    } else {
        const int stride = g_wide ? 2 : 1;
        for (int i = base; i < n; ++i) do_add((unsigned)vals[i * stride]);
    }
}

// -------------------------------------------------------------- query ----
__device__ __forceinline__ float do_query(unsigned int v) {
    unsigned int pos = (v * PRIME) & BIT_MASK;
    unsigned int c   = pos >> 7;                  // 128-bit chunk
    unsigned int t   = pos & 127u;
    const ulonglong2* p2 = reinterpret_cast<const ulonglong2*>(g_bits);
    ulonglong2 B = __ldg(&p2[c]);
    unsigned long long lo = (t & 64u) ? B.y : B.x;
    unsigned int s = t & 63u;
    unsigned long long field = lo >> s;
    if (s > 57u) {                                // field straddles 'lo'
        unsigned long long hi;
        if (t & 64u) hi = __ldg(&g_bits[(2u * c + 2u) & WORD_MASK]);  // 4.7%
        else         hi = B.y;                                         // free
        field |= hi << (64u - s);
    }
    return ((field & 0x7Full) == 0x7Full) ? 1.0f : 0.0f;
}

__global__ void query_kernel(const int* __restrict__ q,
                             float* __restrict__ out, int n) {
    int base = (blockIdx.x * blockDim.x + threadIdx.x) * 4;
    if (base + 3 < n) {
        unsigned int v0, v1, v2, v3;
        if (g_wide) {
            int4 a = *reinterpret_cast<const int4*>(q + 2 * base);
            int4 b = *reinterpret_cast<const int4*>(q + 2 * base + 4);
            v0 = (unsigned)a.x; v1 = (unsigned)a.z;
            v2 = (unsigned)b.x; v3 = (unsigned)b.z;
        } else {
            int4 a = *reinterpret_cast<const int4*>(q + base);
            v0 = (unsigned)a.x; v1 = (unsigned)a.y;
            v2 = (unsigned)a.z; v3 = (unsigned)a.w;
        }
        float4 r;
        r.x = do_query(v0); r.y = do_query(v1);
        r.z = do_query(v2); r.w = do_query(v3);
        *reinterpret_cast<float4*>(out + base) = r;
    } else {
        const int stride = g_wide ? 2 : 1;
        for (int i = base; i < n; ++i)
            out[i] = do_query((unsigned)q[i * stride]);
    }
}

// ----------------------------------------------------------- launcher ----
extern "C" void kernel_launch(void* const* d_in, const int* in_sizes, int n_in,
                              void* d_out, int out_size) {
    const int* add_values   = (const int*)d_in[0];
    const int* query_values = (const int*)d_in[1];
    float*     out          = (float*)d_out;
    int n_add = in_sizes[0];
    int n_qry = in_sizes[1];

    clear_kernel<<<2048, 256>>>(add_values);
    add_kernel<<<(n_add + 1023) / 1024, 256>>>(add_values, n_add);
    query_kernel<<<(n_qry + 1023) / 1024, 256>>>(query_values, out, n_qry);
}